// round 1
// baseline (speedup 1.0000x reference)
#include <cuda_runtime.h>

#define BB 512
#define SS 200
#define HH 256

// Scratch (no cudaMalloc allowed)
__device__ float g_l[BB * HH];        // l[b,k] = W_meta(last_memory)
__device__ float g_scores[BB * SS];   // pre-softmax attention scores

__device__ __forceinline__ float tanh_fast(float x) {
    // tanh(x) = 1 - 2/(e^{2x}+1); MUFU EX2/RCP ~1e-6 rel err, handles +-inf limits.
    float e = __expf(2.0f * x);
    return 1.0f - 2.0f / (e + 1.0f);
}

// ---------------------------------------------------------------------------
// Kernel C: l[b,k] = sum_h W[k,h] * last_memory[b,h]
// One CTA per batch. W staged transposed through smem with coalesced loads.
// ---------------------------------------------------------------------------
__global__ void __launch_bounds__(256) l_kernel(const float* __restrict__ lastm,
                                                const float* __restrict__ W) {
    __shared__ float lm[HH];
    __shared__ float Wt[32][HH + 1];   // stride 257: conflict-free store & read
    const int b = blockIdx.x;
    const int tid = threadIdx.x;

    lm[tid] = lastm[b * HH + tid];
    __syncthreads();

    float acc = 0.0f;
    for (int h0 = 0; h0 < HH; h0 += 32) {
#pragma unroll
        for (int q = 0; q < 8; q++) {
            int f = tid + 256 * q;       // linear float4 index over 256k x 8
            int k = f >> 3;
            int hq = f & 7;
            float4 v = *(const float4*)(W + k * HH + h0 + hq * 4);
            Wt[hq * 4 + 0][k] = v.x;
            Wt[hq * 4 + 1][k] = v.y;
            Wt[hq * 4 + 2][k] = v.z;
            Wt[hq * 4 + 3][k] = v.w;
        }
        __syncthreads();
#pragma unroll
        for (int hh = 0; hh < 32; hh++)
            acc = fmaf(Wt[hh][tid], lm[h0 + hh], acc);
        __syncthreads();
    }
    g_l[b * HH + tid] = acc;
}

// ---------------------------------------------------------------------------
// Kernel A: scores[b,s] = sum_k V[k] * tanh( (X[b,s,:] . U[k,:]) + l[b,k] )
// CTA = (batch, s-tile of 8*NI rows). 256 threads = 32 tk x 8 ts.
// Thread computes NI s-rows x 8 k-cols, k paired (tk+64p, tk+64p+32) into
// packed f32x2 accumulators -> fma.rn.f32x2 (2x fp32 FMA throughput).
// ---------------------------------------------------------------------------
template <int NI>
__global__ void __launch_bounds__(256, 2) scores_kernel(const float* __restrict__ X,
                                                        const float* __restrict__ U,
                                                        const float* __restrict__ Vv,
                                                        int s0_in) {
    constexpr int STILE = 8 * NI;
    __shared__ float Usm[32][HH + 1];    // [h][k], stride 257
    __shared__ float Xsm[STILE][40];     // [s][h], padded row
    __shared__ float lsm[HH];
    __shared__ float vsm[HH];

    const int b = blockIdx.x;
    const int s0 = (NI == 8) ? (int)blockIdx.y * 64 : s0_in;
    const int tid = threadIdx.x;
    const int tk = tid & 31;
    const int ts = tid >> 5;

    lsm[tid] = g_l[b * HH + tid];
    vsm[tid] = Vv[tid];

    unsigned long long acc[NI][4];
#pragma unroll
    for (int i = 0; i < NI; i++)
#pragma unroll
        for (int p = 0; p < 4; p++) acc[i][p] = 0ull;

    const float* Xb = X + (size_t)b * SS * HH;

    for (int h0 = 0; h0 < HH; h0 += 32) {
        // Stage U[k][h0..h0+31] transposed into Usm[h][k]
#pragma unroll
        for (int q = 0; q < 8; q++) {
            int f = tid + 256 * q;
            int k = f >> 3;
            int hq = f & 7;
            float4 v = *(const float4*)(U + k * HH + h0 + hq * 4);
            Usm[hq * 4 + 0][k] = v.x;
            Usm[hq * 4 + 1][k] = v.y;
            Usm[hq * 4 + 2][k] = v.z;
            Usm[hq * 4 + 3][k] = v.w;
        }
        // Stage X tile (rows are always in-bounds by launch construction)
        for (int f = tid; f < STILE * 8; f += 256) {
            int s = f >> 3;
            int hq = f & 7;
            float4 v = *(const float4*)(Xb + (s0 + s) * HH + h0 + hq * 4);
            *(float4*)&Xsm[s][hq * 4] = v;
        }
        __syncthreads();

#pragma unroll 8
        for (int hh = 0; hh < 32; hh++) {
            // u values at k = tk + 32*j, j<8; pack pairs (j=2p, j=2p+1)
            float u[8];
#pragma unroll
            for (int j = 0; j < 8; j++) u[j] = Usm[hh][tk + 32 * j];
            unsigned long long u2[4];
#pragma unroll
            for (int p = 0; p < 4; p++)
                asm("mov.b64 %0, {%1, %2};" : "=l"(u2[p]) : "f"(u[2 * p]), "f"(u[2 * p + 1]));
#pragma unroll
            for (int i = 0; i < NI; i++) {
                float xv = Xsm[ts * NI + i][hh];   // broadcast across warp lanes
                unsigned long long x2;
                asm("mov.b64 %0, {%1, %1};" : "=l"(x2) : "f"(xv));
#pragma unroll
                for (int p = 0; p < 4; p++)
                    asm("fma.rn.f32x2 %0, %1, %2, %0;"
                        : "+l"(acc[i][p]) : "l"(x2), "l"(u2[p]));
            }
        }
        __syncthreads();
    }

    // Epilogue: tanh, dot with V, warp-reduce over k (lanes of a warp share ts)
#pragma unroll
    for (int i = 0; i < NI; i++) {
        float sum = 0.0f;
#pragma unroll
        for (int p = 0; p < 4; p++) {
            float alo, ahi;
            asm("mov.b64 {%0, %1}, %2;" : "=f"(alo), "=f"(ahi) : "l"(acc[i][p]));
            int k0 = tk + 64 * p;        // j = 2p
            int k1 = tk + 64 * p + 32;   // j = 2p+1
            sum = fmaf(vsm[k0], tanh_fast(alo + lsm[k0]), sum);
            sum = fmaf(vsm[k1], tanh_fast(ahi + lsm[k1]), sum);
        }
#pragma unroll
        for (int off = 16; off; off >>= 1)
            sum += __shfl_xor_sync(0xffffffffu, sum, off);
        if (tk == 0) g_scores[b * SS + s0 + ts * NI + i] = sum;
    }
}

// ---------------------------------------------------------------------------
// Kernel B: softmax over S, pooled[h] = sum_s alpha_s X[b,s,h],
//           out[b,:] = MetaW @ pooled + Metab
// ---------------------------------------------------------------------------
__global__ void __launch_bounds__(256) pool_kernel(const float* __restrict__ X,
                                                   const float* __restrict__ MW,
                                                   const float* __restrict__ Mb,
                                                   float* __restrict__ out) {
    __shared__ float sal[SS];
    __shared__ float red[8];
    __shared__ float4 red4[8];

    const int b = blockIdx.x;
    const int tid = threadIdx.x;
    const int lane = tid & 31;
    const int w = tid >> 5;

    float v = (tid < SS) ? g_scores[b * SS + tid] : __int_as_float(0xff800000);
    float m = v;
#pragma unroll
    for (int o = 16; o; o >>= 1) m = fmaxf(m, __shfl_xor_sync(0xffffffffu, m, o));
    if (lane == 0) red[w] = m;
    __syncthreads();
    float bm = red[0];
#pragma unroll
    for (int i = 1; i < 8; i++) bm = fmaxf(bm, red[i]);

    float e = (tid < SS) ? __expf(v - bm) : 0.0f;
    float s = e;
#pragma unroll
    for (int o = 16; o; o >>= 1) s += __shfl_xor_sync(0xffffffffu, s, o);
    __syncthreads();
    if (lane == 0) red[w] = s;
    __syncthreads();
    float bs = 0.0f;
#pragma unroll
    for (int i = 0; i < 8; i++) bs += red[i];

    if (tid < SS) sal[tid] = e / bs;
    __syncthreads();

    // Pooling: thread = h (coalesced 1KB rows across the CTA)
    const float* Xb = X + (size_t)b * SS * HH + tid;
    float acc = 0.0f;
#pragma unroll 8
    for (int sdx = 0; sdx < SS; sdx++)
        acc = fmaf(sal[sdx], Xb[(size_t)sdx * HH], acc);

    // Final projection to 4 outputs
    float4 p;
    p.x = acc * MW[0 * HH + tid];
    p.y = acc * MW[1 * HH + tid];
    p.z = acc * MW[2 * HH + tid];
    p.w = acc * MW[3 * HH + tid];
#pragma unroll
    for (int o = 16; o; o >>= 1) {
        p.x += __shfl_xor_sync(0xffffffffu, p.x, o);
        p.y += __shfl_xor_sync(0xffffffffu, p.y, o);
        p.z += __shfl_xor_sync(0xffffffffu, p.z, o);
        p.w += __shfl_xor_sync(0xffffffffu, p.w, o);
    }
    if (lane == 0) red4[w] = p;
    __syncthreads();
    if (tid == 0) {
        float4 t = red4[0];
#pragma unroll
        for (int i = 1; i < 8; i++) {
            t.x += red4[i].x; t.y += red4[i].y; t.z += red4[i].z; t.w += red4[i].w;
        }
        out[b * 4 + 0] = t.x + Mb[0];
        out[b * 4 + 1] = t.y + Mb[1];
        out[b * 4 + 2] = t.z + Mb[2];
        out[b * 4 + 3] = t.w + Mb[3];
    }
}

// ---------------------------------------------------------------------------
extern "C" void kernel_launch(void* const* d_in, const int* in_sizes, int n_in,
                              void* d_out, int out_size) {
    const float* X     = (const float*)d_in[0];  // all_memory [B,S,H]
    const float* lastm = (const float*)d_in[1];  // last_memory [B,H]
    const float* U     = (const float*)d_in[2];  // [H,H]
    const float* W     = (const float*)d_in[3];  // [H,H]
    const float* Vv    = (const float*)d_in[4];  // [H,1]
    const float* MW    = (const float*)d_in[5];  // [4,H]
    const float* Mb    = (const float*)d_in[6];  // [4]
    float* out = (float*)d_out;

    l_kernel<<<BB, 256>>>(lastm, W);
    scores_kernel<8><<<dim3(BB, 3), 256>>>(X, U, Vv, 0);    // s = 0..191
    scores_kernel<1><<<dim3(BB, 1), 256>>>(X, U, Vv, 192);  // s = 192..199
    pool_kernel<<<BB, 256>>>(X, MW, Mb, out);
}

// round 3
// speedup vs baseline: 2.0363x; 2.0363x over previous
#include <cuda_runtime.h>
#include <cuda_bf16.h>
#include <cstdint>

#define BB 512
#define SS 200
#define HH 256
#define MROWS (BB * SS)        // 102400 = 800 * 128
#define MTILES 800
#define KCH 4                  // K chunks of 64
#define BLK_ELEMS (128 * 64)   // one swizzled block (bf16) = 16KB

// ---------------- scratch (no cudaMalloc allowed) ----------------
__device__ float g_l[BB * HH];
__device__ float g_sc[MROWS];
__device__ __align__(128) __nv_bfloat16 g_Xhi[MTILES * KCH * BLK_ELEMS];
__device__ __align__(128) __nv_bfloat16 g_Xlo[MTILES * KCH * BLK_ELEMS];
__device__ __align__(128) __nv_bfloat16 g_Uhi[2 * KCH * BLK_ELEMS];
__device__ __align__(128) __nv_bfloat16 g_Ulo[2 * KCH * BLK_ELEMS];

// ---------------- helpers ----------------
__device__ __forceinline__ uint32_t smem_u32(const void* p) {
    uint32_t a;
    asm("{ .reg .u64 t; cvta.to.shared.u64 t, %1; cvt.u32.u64 %0, t; }" : "=r"(a) : "l"(p));
    return a;
}
__device__ __forceinline__ uint32_t sw128(uint32_t o) { return o ^ ((o >> 3) & 0x70); }

__device__ __forceinline__ uint32_t pack_bf2(float x, float y) {
    uint32_t a = (uint32_t)__bfloat16_as_ushort(__float2bfloat16_rn(x));
    uint32_t b = (uint32_t)__bfloat16_as_ushort(__float2bfloat16_rn(y));
    return a | (b << 16);
}

// MUFU-free tanh: exp2 range reduction (FMA poly + int exponent insert) +
// bit-trick reciprocal with 3 Newton iters. |err| <= ~3.4e-5 (clamp at 5.5).
__device__ __forceinline__ float tanh_fma(float x) {
    float t = fminf(fabsf(x), 5.5f) * 2.8853900817779268f;  // 2*log2(e)*|x|
    int n = __float2int_rn(t);
    float f = t - (float)n;                                  // [-0.5, 0.5]
    float p = 1.5403530393381608e-4f;
    p = fmaf(p, f, 1.3333558146428443e-3f);
    p = fmaf(p, f, 9.6181291076284772e-3f);
    p = fmaf(p, f, 5.5504108664821580e-2f);
    p = fmaf(p, f, 2.4022650695910071e-1f);
    p = fmaf(p, f, 6.9314718055994531e-1f);
    p = fmaf(p, f, 1.0f);                                    // 2^f
    float E = __int_as_float(__float_as_int(p) + (n << 23)); // e^{2|x|}
    float D = E + 1.0f;
    float r = __int_as_float(0x7EF311C3 - __float_as_int(D));
    r = r * fmaf(-D, r, 2.0f);
    r = r * fmaf(-D, r, 2.0f);
    r = r * fmaf(-D, r, 2.0f);                               // 1/(E+1)
    float y = fmaf(-2.0f, r, 1.0f);                          // tanh(|x|)
    return copysignf(y, x);
}

__device__ __forceinline__ void ldsm4(uint32_t* r, uint32_t addr) {
    asm volatile("ldmatrix.sync.aligned.m8n8.x4.shared.b16 {%0,%1,%2,%3}, [%4];"
                 : "=r"(r[0]), "=r"(r[1]), "=r"(r[2]), "=r"(r[3]) : "r"(addr));
}
__device__ __forceinline__ void mma_bf16(float* c, const uint32_t* a, uint32_t b0, uint32_t b1) {
    asm volatile(
        "mma.sync.aligned.m16n8k16.row.col.f32.bf16.bf16.f32 "
        "{%0,%1,%2,%3}, {%4,%5,%6,%7}, {%8,%9}, {%0,%1,%2,%3};"
        : "+f"(c[0]), "+f"(c[1]), "+f"(c[2]), "+f"(c[3])
        : "r"(a[0]), "r"(a[1]), "r"(a[2]), "r"(a[3]), "r"(b0), "r"(b1));
}
#define CPA16(dst, src) \
    asm volatile("cp.async.cg.shared.global [%0], [%1], 16;" :: "r"(dst), "l"(src))

// ---------------------------------------------------------------------------
// conv: fp32 -> bf16 (hi, lo) pre-swizzled SW128 128x64 blocks.
// blockIdx = tile*4 + kchunk.
// ---------------------------------------------------------------------------
__global__ void __launch_bounds__(128) conv_kernel(const float* __restrict__ S,
                                                   __nv_bfloat16* __restrict__ DH,
                                                   __nv_bfloat16* __restrict__ DL) {
    const int blk = blockIdx.x;
    const int mt = blk >> 2;
    const int c = blk & 3;
    const int tid = threadIdx.x;
    char* dh = (char*)(DH + (size_t)blk * BLK_ELEMS);
    char* dl = (char*)(DL + (size_t)blk * BLK_ELEMS);

#pragma unroll 4
    for (int it = 0; it < 16; it++) {
        int f = it * 128 + tid;
        int row = f >> 4;
        int q = f & 15;
        float4 v = *(const float4*)(S + ((size_t)(mt * 128 + row)) * HH + c * 64 + q * 4);
        float4 h;
        h.x = __bfloat162float(__float2bfloat16_rn(v.x));
        h.y = __bfloat162float(__float2bfloat16_rn(v.y));
        h.z = __bfloat162float(__float2bfloat16_rn(v.z));
        h.w = __bfloat162float(__float2bfloat16_rn(v.w));
        uint2 ph, pl;
        ph.x = pack_bf2(v.x, v.y);
        ph.y = pack_bf2(v.z, v.w);
        pl.x = pack_bf2(v.x - h.x, v.y - h.y);
        pl.y = pack_bf2(v.z - h.z, v.w - h.w);
        uint32_t off = sw128((uint32_t)(row * 128 + (q >> 1) * 16)) + (q & 1) * 8;
        *(uint2*)(dh + off) = ph;
        *(uint2*)(dl + off) = pl;
    }
}

// ---------------------------------------------------------------------------
// l[b,k] = sum_h W[k,h] * last_memory[b,h]
// ---------------------------------------------------------------------------
__global__ void __launch_bounds__(256) l_kernel(const float* __restrict__ lastm,
                                                const float* __restrict__ W) {
    __shared__ float lm[HH];
    __shared__ float Wt[32][HH + 1];
    const int b = blockIdx.x;
    const int tid = threadIdx.x;

    lm[tid] = lastm[b * HH + tid];
    __syncthreads();

    float acc = 0.0f;
    for (int h0 = 0; h0 < HH; h0 += 32) {
#pragma unroll
        for (int q = 0; q < 8; q++) {
            int f = tid + 256 * q;
            int k = f >> 3;
            int hq = f & 7;
            float4 v = *(const float4*)(W + k * HH + h0 + hq * 4);
            Wt[hq * 4 + 0][k] = v.x;
            Wt[hq * 4 + 1][k] = v.y;
            Wt[hq * 4 + 2][k] = v.z;
            Wt[hq * 4 + 3][k] = v.w;
        }
        __syncthreads();
#pragma unroll
        for (int hh = 0; hh < 32; hh++)
            acc = fmaf(Wt[hh][tid], lm[h0 + hh], acc);
        __syncthreads();
    }
    g_l[b * HH + tid] = acc;
}

// ---------------------------------------------------------------------------
// GEMM via mma.sync bf16 split-3 + fused tanh/V epilogue.
// CTA: 128 rows x 256 cols, 512 threads = 16 warps (4m x 4n), warp 32x64.
// Stage (per K-chunk of 64): Xhi|Xlo|Uhi0|Uhi1|Ulo0|Ulo1 = 96KB, double-buffered.
// ---------------------------------------------------------------------------
constexpr uint32_t STG = 98304;          // 96KB per stage
constexpr uint32_t GEMM_SMEM = 2 * STG;  // 192KB dynamic

__global__ void __launch_bounds__(512, 1) gemm_kernel(const float* __restrict__ Vv) {
    extern __shared__ __align__(1024) char smem[];
    __shared__ float vsm[256];
    __shared__ float s_red[4][128];

    const uint32_t sb = smem_u32(smem);
    const int tid = threadIdx.x;
    const int lane = tid & 31;
    const int wid = tid >> 5;
    const int wm = wid & 3;
    const int wn = wid >> 2;
    const int m = blockIdx.x;

    if (tid < 256) vsm[tid] = Vv[tid];

    float acc[2][8][4];
#pragma unroll
    for (int i = 0; i < 2; i++)
#pragma unroll
        for (int j = 0; j < 8; j++)
#pragma unroll
            for (int k = 0; k < 4; k++) acc[i][j][k] = 0.0f;

    // stage loader: 6 regions x 16KB; each thread: 2 x 16B per region
    auto stage = [&](int kc, uint32_t sbase) {
        const char* xh = (const char*)(g_Xhi + (size_t)(m * 4 + kc) * BLK_ELEMS);
        const char* xl = (const char*)(g_Xlo + (size_t)(m * 4 + kc) * BLK_ELEMS);
        const char* u0h = (const char*)(g_Uhi + (size_t)(0 * 4 + kc) * BLK_ELEMS);
        const char* u1h = (const char*)(g_Uhi + (size_t)(1 * 4 + kc) * BLK_ELEMS);
        const char* u0l = (const char*)(g_Ulo + (size_t)(0 * 4 + kc) * BLK_ELEMS);
        const char* u1l = (const char*)(g_Ulo + (size_t)(1 * 4 + kc) * BLK_ELEMS);
        uint32_t d = sbase + tid * 16;
        uint32_t o = tid * 16;
        CPA16(d + 0u,      xh + o);  CPA16(d + 0u + 8192,      xh + o + 8192);
        CPA16(d + 16384u,  xl + o);  CPA16(d + 16384u + 8192,  xl + o + 8192);
        CPA16(d + 32768u,  u0h + o); CPA16(d + 32768u + 8192,  u0h + o + 8192);
        CPA16(d + 49152u,  u1h + o); CPA16(d + 49152u + 8192,  u1h + o + 8192);
        CPA16(d + 65536u,  u0l + o); CPA16(d + 65536u + 8192,  u0l + o + 8192);
        CPA16(d + 81920u,  u1l + o); CPA16(d + 81920u + 8192,  u1l + o + 8192);
        asm volatile("cp.async.commit_group;");
    };

    stage(0, sb);

    // ldmatrix lane addressing (within 128x64 SW128 block)
    const int arow = wm * 32 + (lane & 7) + (lane & 8);     // + mt*16
    const int akb = (lane >> 4) * 16;                        // + k0*32
    const int brow0 = (wn & 1) * 64 + (lane & 7) + ((lane >> 4) << 3);  // + ntp*16
    const int bkb = ((lane >> 3) & 1) * 16;                  // + k0*32
    const uint32_t ubase = 32768u + (uint32_t)(wn >> 1) * 16384u;

    for (int kc = 0; kc < KCH; kc++) {
        const uint32_t cur = sb + (uint32_t)(kc & 1) * STG;
        if (kc + 1 < KCH) {
            stage(kc + 1, sb + (uint32_t)((kc + 1) & 1) * STG);
            asm volatile("cp.async.wait_group 1;");
        } else {
            asm volatile("cp.async.wait_group 0;");
        }
        __syncthreads();

#pragma unroll
        for (int k0 = 0; k0 < 4; k0++) {
            const uint32_t kb = k0 * 32;
            uint32_t Ahi[2][4], Alo[2][4];
#pragma unroll
            for (int mt = 0; mt < 2; mt++) {
                uint32_t roff = (uint32_t)((arow + mt * 16) * 128);
                ldsm4(Ahi[mt], cur + sw128(roff + kb + akb));
                ldsm4(Alo[mt], cur + 16384u + sw128(roff + kb + akb));
            }
#pragma unroll
            for (int ntp = 0; ntp < 4; ntp++) {
                uint32_t roff = (uint32_t)((brow0 + ntp * 16) * 128);
                uint32_t bh[4], bl[4];
                ldsm4(bh, cur + ubase + sw128(roff + kb + bkb));
                ldsm4(bl, cur + ubase + 32768u + sw128(roff + kb + bkb));
#pragma unroll
                for (int mt = 0; mt < 2; mt++) {
#pragma unroll
                    for (int sub = 0; sub < 2; sub++) {
                        float* c = acc[mt][ntp * 2 + sub];
                        mma_bf16(c, Ahi[mt], bh[sub * 2], bh[sub * 2 + 1]);
                        mma_bf16(c, Ahi[mt], bl[sub * 2], bl[sub * 2 + 1]);
                        mma_bf16(c, Alo[mt], bh[sub * 2], bh[sub * 2 + 1]);
                    }
                }
            }
        }
        __syncthreads();
    }

    // Epilogue: per row, sum_n V[n]*tanh(acc + l[b,n]); reduce quad -> warps
#pragma unroll
    for (int mt = 0; mt < 2; mt++) {
#pragma unroll
        for (int rh = 0; rh < 2; rh++) {
            int rowl = wm * 32 + mt * 16 + (lane >> 2) + rh * 8;
            int rowg = m * 128 + rowl;
            const float* lr = g_l + (rowg / SS) * HH;
            float s = 0.0f;
#pragma unroll
            for (int nt = 0; nt < 8; nt++) {
#pragma unroll
                for (int cl = 0; cl < 2; cl++) {
                    int col = wn * 64 + nt * 8 + (lane & 3) * 2 + cl;
                    float v = acc[mt][nt][rh * 2 + cl] + __ldg(lr + col);
                    s = fmaf(vsm[col], tanh_fma(v), s);
                }
            }
            s += __shfl_xor_sync(0xffffffffu, s, 1);
            s += __shfl_xor_sync(0xffffffffu, s, 2);
            if ((lane & 3) == 0) s_red[wn][rowl] = s;
        }
    }
    __syncthreads();
    if (tid < 128)
        g_sc[m * 128 + tid] = s_red[0][tid] + s_red[1][tid] + s_red[2][tid] + s_red[3][tid];
}

// ---------------------------------------------------------------------------
// softmax over S + pooled + final projection
// ---------------------------------------------------------------------------
__global__ void __launch_bounds__(256) pool_kernel(const float* __restrict__ X,
                                                   const float* __restrict__ MW,
                                                   const float* __restrict__ Mb,
                                                   float* __restrict__ out) {
    __shared__ float sal[SS];
    __shared__ float red[8];
    __shared__ float4 red4[8];

    const int b = blockIdx.x;
    const int tid = threadIdx.x;
    const int lane = tid & 31;
    const int w = tid >> 5;

    float v = (tid < SS) ? g_sc[b * SS + tid] : __int_as_float(0xff800000);
    float mx = v;
#pragma unroll
    for (int o = 16; o; o >>= 1) mx = fmaxf(mx, __shfl_xor_sync(0xffffffffu, mx, o));
    if (lane == 0) red[w] = mx;
    __syncthreads();
    float bm = red[0];
#pragma unroll
    for (int i = 1; i < 8; i++) bm = fmaxf(bm, red[i]);

    float e = (tid < SS) ? __expf(v - bm) : 0.0f;
    float s = e;
#pragma unroll
    for (int o = 16; o; o >>= 1) s += __shfl_xor_sync(0xffffffffu, s, o);
    __syncthreads();
    if (lane == 0) red[w] = s;
    __syncthreads();
    float bs = 0.0f;
#pragma unroll
    for (int i = 0; i < 8; i++) bs += red[i];

    if (tid < SS) sal[tid] = e / bs;
    __syncthreads();

    const float* Xb = X + (size_t)b * SS * HH + tid;
    float acc = 0.0f;
#pragma unroll 8
    for (int sdx = 0; sdx < SS; sdx++)
        acc = fmaf(sal[sdx], Xb[(size_t)sdx * HH], acc);

    float4 p;
    p.x = acc * MW[0 * HH + tid];
    p.y = acc * MW[1 * HH + tid];
    p.z = acc * MW[2 * HH + tid];
    p.w = acc * MW[3 * HH + tid];
#pragma unroll
    for (int o = 16; o; o >>= 1) {
        p.x += __shfl_xor_sync(0xffffffffu, p.x, o);
        p.y += __shfl_xor_sync(0xffffffffu, p.y, o);
        p.z += __shfl_xor_sync(0xffffffffu, p.z, o);
        p.w += __shfl_xor_sync(0xffffffffu, p.w, o);
    }
    if (lane == 0) red4[w] = p;
    __syncthreads();
    if (tid == 0) {
        float4 t = red4[0];
#pragma unroll
        for (int i = 1; i < 8; i++) {
            t.x += red4[i].x; t.y += red4[i].y; t.z += red4[i].z; t.w += red4[i].w;
        }
        out[b * 4 + 0] = t.x + Mb[0];
        out[b * 4 + 1] = t.y + Mb[1];
        out[b * 4 + 2] = t.z + Mb[2];
        out[b * 4 + 3] = t.w + Mb[3];
    }
}

// ---------------------------------------------------------------------------
extern "C" void kernel_launch(void* const* d_in, const int* in_sizes, int n_in,
                              void* d_out, int out_size) {
    const float* X     = (const float*)d_in[0];
    const float* lastm = (const float*)d_in[1];
    const float* U     = (const float*)d_in[2];
    const float* W     = (const float*)d_in[3];
    const float* Vv    = (const float*)d_in[4];
    const float* MW    = (const float*)d_in[5];
    const float* Mb    = (const float*)d_in[6];
    float* out = (float*)d_out;

    __nv_bfloat16 *xhi, *xlo, *uhi, *ulo;
    cudaGetSymbolAddress((void**)&xhi, g_Xhi);
    cudaGetSymbolAddress((void**)&xlo, g_Xlo);
    cudaGetSymbolAddress((void**)&uhi, g_Uhi);
    cudaGetSymbolAddress((void**)&ulo, g_Ulo);

    cudaFuncSetAttribute(gemm_kernel, cudaFuncAttributeMaxDynamicSharedMemorySize, GEMM_SMEM);

    conv_kernel<<<MTILES * KCH, 128>>>(X, xhi, xlo);
    conv_kernel<<<2 * KCH, 128>>>(U, uhi, ulo);
    l_kernel<<<BB, 256>>>(lastm, W);
    gemm_kernel<<<MTILES, 512, GEMM_SMEM>>>(Vv);
    pool_kernel<<<BB, 256>>>(X, MW, Mb, out);
}